// round 5
// baseline (speedup 1.0000x reference)
#include <cuda_runtime.h>
#include <cstdint>

#define D      1024
#define BS     80
#define NBATCH 16
#define STEPN  5
#define ALPHA  0.01f
#define NBLK   128
#define NTHR   512
#define QW     132             // q smem row stride (floats)
#define WSTR   1032            // W smem col stride (floats): 1032%32=8 -> conflict-free
#define WFL    (16 * WSTR)     // 16512 floats
#define QBUF   (40 * QW)       // 5280 floats per buffer
#define DYN_FL (WFL + 2 * QBUF)

// ---- global scratch (no device alloc allowed) ----
__device__ __align__(16) float g_q[BS * D];
__device__ __align__(16) float g_y[BS * D];
__device__ __align__(16) float g_csum[2][D];
__device__ __align__(16) float g_csq[2][D];
__device__ unsigned g_bar0, g_bar1, g_depart;

// ---- packed fp32x2 helpers ----
__device__ __forceinline__ void ffma2(unsigned long long& acc,
                                      unsigned long long a,
                                      unsigned long long b) {
    asm("fma.rn.f32x2 %0, %1, %2, %0;" : "+l"(acc) : "l"(a), "l"(b));
}
__device__ __forceinline__ float fold2(unsigned long long v) {
    float lo, hi;
    asm("mov.b64 {%0, %1}, %2;" : "=f"(lo), "=f"(hi) : "l"(v));
    return lo + hi;
}

// ---- cp.async helpers ----
__device__ __forceinline__ void cp_async16(uint32_t saddr, const void* gptr) {
    asm volatile("cp.async.cg.shared.global [%0], [%1], 16;"
                 :: "r"(saddr), "l"(gptr));
}
__device__ __forceinline__ uint32_t s2u(const void* p) {
    return (uint32_t)__cvta_generic_to_shared(p);
}
#define CP_COMMIT() asm volatile("cp.async.commit_group;")

// ---- software grid barrier (single-wave grid; replay-safe) ----
__device__ __forceinline__ void gridbar(unsigned* cnt) {
    __syncthreads();
    if (threadIdx.x == 0) {
        __threadfence();
        atomicAdd(cnt, 1u);
        while (*(volatile unsigned*)cnt < NBLK) { }
        __threadfence();
    }
    __syncthreads();
}

__global__ void __launch_bounds__(NTHR, 1)
fused_kernel(const float* __restrict__ x, const float* __restrict__ W,
             const float* __restrict__ bias, const float* __restrict__ gamma,
             const float* __restrict__ beta, float* __restrict__ out) {
    extern __shared__ __align__(16) float dynsm[];
    float* smW  = dynsm;          // [16][WSTR]
    float* qbuf = dynsm + WFL;    // 2 x [40][QW]; epilogue staging aliases this

    __shared__ float ys[40 * 16];
    __shared__ float sred[STEPN][16];
    __shared__ float sd[STEPN];
    __shared__ float s_r[8];
    __shared__ float s_tot;

    const int tid = threadIdx.x;
    const int bid = blockIdx.x;
    const int rh = bid >> 6;
    const int r0 = rh * 40;
    const int c0 = (bid & 63) * 16;

    // ---- issue W tile prefetch to smem (hidden under phase 1 + barrier) ----
#pragma unroll
    for (int i = tid; i < 4096; i += NTHR) {     // 16 cols x 256 16B-chunks
        int c = i >> 8, v = i & 255;
        cp_async16(s2u(smW + c * WSTR + v * 4), W + (c0 + c) * D + v * 4);
    }
    CP_COMMIT();                                  // group: W

    // ================= phase 1: q rows (blocks 0..79) =================
    if (bid < BS) {
        const int n = bid;
        const int b = n % NBATCH;
        const int s = n / NBATCH;
        const int rb = b * STEPN;

        float pd[STEPN] = {0.f, 0.f, 0.f, 0.f, 0.f};
        const float* xn = x + n * D;
        for (int j = tid; j < D; j += NTHR) {
            float v = xn[j];
#pragma unroll
            for (int t = 0; t < STEPN; t++)
                pd[t] += x[(rb + t) * D + j] * v;
        }
#pragma unroll
        for (int t = 0; t < STEPN; t++) {
            float v = pd[t];
#pragma unroll
            for (int o = 16; o > 0; o >>= 1)
                v += __shfl_down_sync(0xffffffffu, v, o);
            if ((tid & 31) == 0) sred[t][tid >> 5] = v;
        }
        __syncthreads();
        if (tid < STEPN) {
            float v = 0.f;
#pragma unroll
            for (int w = 0; w < 16; w++) v += sred[tid][w];
            sd[tid] = ALPHA * v;
        }
        __syncthreads();
        for (int i = tid; i < D; i += NTHR) {
            float g = 0.f;
            for (int t = 0; t <= s; t++) {
                float xv = x[(rb + t) * D + i];
                g = g * (1.f - ALPHA * xv * xv) + xv * sd[t];
            }
            g_q[n * D + i] = g;
        }
    }

    gridbar(&g_bar0);

    // ================= phase 2: GEMM (W resident in smem) ==================
    {
        const int w  = tid >> 5;
        const int lane = tid & 31;
        const int rg = lane >> 2;
        const int cg = lane & 3;

        unsigned long long acc[5][4];
#pragma unroll
        for (int m = 0; m < 5; m++)
#pragma unroll
            for (int c = 0; c < 4; c++) acc[m][c] = 0ull;

        auto issue_q = [&](int ch) {
            const int kb = ch * 128;
            float* bq = qbuf + (ch & 1) * QBUF;
#pragma unroll
            for (int i = tid; i < 1280; i += NTHR) {
                int r = i >> 5, v = i & 31;
                cp_async16(s2u(bq + r * QW + v * 4),
                           g_q + (r0 + r) * D + kb + v * 4);
            }
            CP_COMMIT();
        };

        issue_q(0);
        issue_q(1);
        for (int ch = 0; ch < 8; ch++) {
            if (ch < 7) asm volatile("cp.async.wait_group 1;");
            else        asm volatile("cp.async.wait_group 0;");
            __syncthreads();

            const float* bq = qbuf + (ch & 1) * QBUF + (rg * 5) * QW + w * 8;
            const float* bw = smW + cg * WSTR + ch * 128 + w * 8;
#pragma unroll
            for (int qd = 0; qd < 2; qd++) {
                const int k4 = qd * 4;
                ulonglong2 qv[5];
#pragma unroll
                for (int m = 0; m < 5; m++)
                    qv[m] = *(const ulonglong2*)(bq + m * QW + k4);
#pragma unroll
                for (int cc = 0; cc < 4; cc++) {
                    ulonglong2 wv = *(const ulonglong2*)(bw + cc * 4 * WSTR + k4);
#pragma unroll
                    for (int m = 0; m < 5; m++) {
                        ffma2(acc[m][cc], qv[m].x, wv.x);
                        ffma2(acc[m][cc], qv[m].y, wv.y);
                    }
                }
            }
            __syncthreads();
            if (ch + 2 < 8) issue_q(ch + 2);
        }

        // stage folded partials into qbuf region (dead now)
        float* stg = qbuf;
        {
            float* dst = stg + w * 640 + lane * 20;
#pragma unroll
            for (int m = 0; m < 5; m++)
#pragma unroll
                for (int cc = 0; cc < 4; cc++)
                    dst[m * 4 + cc] = fold2(acc[m][cc]);
        }
        __syncthreads();

        // 16-way reduce + bias; write y
        for (int idx = tid; idx < 640; idx += NTHR) {
            const int row = idx >> 4, col = idx & 15;
            const int rg2 = row / 5, m = row - rg2 * 5;
            const int cg2 = col & 3, cc = col >> 2;
            const int off = (rg2 * 4 + cg2) * 20 + m * 4 + cc;
            float s = 0.f;
#pragma unroll
            for (int ww = 0; ww < 16; ww++)
                s += stg[ww * 640 + off];
            const float yv = s + bias[c0 + col];
            g_y[(r0 + row) * D + c0 + col] = yv;
            ys[row * 16 + col] = yv;
        }
        __syncthreads();

        // per-column partial stats over this block's 40 rows
        if (tid < 16) {
            float su = 0.f, sq = 0.f;
#pragma unroll
            for (int r = 0; r < 40; r++) {
                float v = ys[r * 16 + tid];
                su += v;
                sq += v * v;
            }
            g_csum[rh][c0 + tid] = su;
            g_csq[rh][c0 + tid]  = sq;
        }
    }

    gridbar(&g_bar1);

    // ================= phase 3: BN + relu + row L2-normalize =================
    {
        const bool act = (bid < BS) && (tid < 256);
        float z[4];
        float ss = 0.f;
        int k0 = tid * 4;
        if (act) {
            const int n = bid;
            float4 y4  = *(const float4*)(g_y + n * D + k0);
            float4 s04 = *(const float4*)(&g_csum[0][k0]);
            float4 s14 = *(const float4*)(&g_csum[1][k0]);
            float4 q04 = *(const float4*)(&g_csq[0][k0]);
            float4 q14 = *(const float4*)(&g_csq[1][k0]);
            float4 ga4 = *(const float4*)(gamma + k0);
            float4 be4 = *(const float4*)(beta + k0);

            const float inv = 1.f / (float)BS;
            float mu, var, rstd;
            mu = (s04.x + s14.x) * inv; var = (q04.x + q14.x) * inv - mu * mu;
            rstd = rsqrtf(var + 1e-5f);
            z[0] = fmaxf((y4.x - mu) * rstd * ga4.x + be4.x, 0.f);
            mu = (s04.y + s14.y) * inv; var = (q04.y + q14.y) * inv - mu * mu;
            rstd = rsqrtf(var + 1e-5f);
            z[1] = fmaxf((y4.y - mu) * rstd * ga4.y + be4.y, 0.f);
            mu = (s04.z + s14.z) * inv; var = (q04.z + q14.z) * inv - mu * mu;
            rstd = rsqrtf(var + 1e-5f);
            z[2] = fmaxf((y4.z - mu) * rstd * ga4.z + be4.z, 0.f);
            mu = (s04.w + s14.w) * inv; var = (q04.w + q14.w) * inv - mu * mu;
            rstd = rsqrtf(var + 1e-5f);
            z[3] = fmaxf((y4.w - mu) * rstd * ga4.w + be4.w, 0.f);

            ss = z[0] * z[0] + z[1] * z[1] + z[2] * z[2] + z[3] * z[3];
#pragma unroll
            for (int o = 16; o > 0; o >>= 1)
                ss += __shfl_down_sync(0xffffffffu, ss, o);
            if ((tid & 31) == 0) s_r[tid >> 5] = ss;
        }
        __syncthreads();
        if (act && tid == 0) {
            float t = 0.f;
#pragma unroll
            for (int w = 0; w < 8; w++) t += s_r[w];
            s_tot = 1.f / fmaxf(sqrtf(t), 1e-12f);
        }
        __syncthreads();
        if (act) {
            float sc = s_tot;
            float4 o4 = make_float4(z[0] * sc, z[1] * sc, z[2] * sc, z[3] * sc);
            *(float4*)(out + bid * D + k0) = o4;
        }
    }

    // ---- depart + replay-safe reset of barrier state ----
    if (threadIdx.x == 0) {
        __threadfence();
        unsigned old = atomicAdd(&g_depart, 1u);
        if (old == NBLK - 1) {
            g_bar0 = 0;
            g_bar1 = 0;
            __threadfence();
            g_depart = 0;
            __threadfence();
        }
    }
}

extern "C" void kernel_launch(void* const* d_in, const int* in_sizes, int n_in,
                              void* d_out, int out_size) {
    (void)in_sizes; (void)n_in; (void)out_size;
    const float* x     = (const float*)d_in[0];
    const float* W     = (const float*)d_in[1];
    const float* bias  = (const float*)d_in[2];
    const float* gamma = (const float*)d_in[3];
    const float* beta  = (const float*)d_in[4];
    float* out = (float*)d_out;

    static int configured = 0;
    if (!configured) {
        cudaFuncSetAttribute(fused_kernel,
                             cudaFuncAttributeMaxDynamicSharedMemorySize,
                             DYN_FL * (int)sizeof(float));
        configured = 1;
    }
    fused_kernel<<<NBLK, NTHR, DYN_FL * sizeof(float)>>>(x, W, bias, gamma, beta, out);
}

// round 6
// speedup vs baseline: 1.1068x; 1.1068x over previous
#include <cuda_runtime.h>
#include <cstdint>

#define D      1024
#define BS     80
#define NBATCH 16
#define STEPN  5
#define ALPHA  0.01f
#define NBLK   128
#define NTHR   512

#define QCH_FL   (40 * 128)          // 5120 floats per q chunk tile
#define WCH_FL   (16 * 128)          // 2048 floats per W chunk tile
#define STG_FL   (QCH_FL + WCH_FL)   // 7168 floats per stage
#define DYN_FL   (2 * STG_FL)        // 14336 floats (56 KB)
#define CHUNK_BYTES 28672u           // (5120 + 2048) * 4

// ---- global scratch (no device alloc allowed) ----
__device__ __align__(16) float g_qt[8 * 80 * 128];        // chunk-major q, swizzled
__device__ __align__(16) float g_Wt[64 * 8 * 16 * 128];   // tile/chunk-major W, swizzled
__device__ __align__(16) float g_y[BS * D];
__device__ __align__(16) float g_csum[2][D];
__device__ __align__(16) float g_csq[2][D];
__device__ unsigned g_bar0, g_bar1, g_depart;

// ---- packed fp32x2 helpers ----
__device__ __forceinline__ void ffma2(unsigned long long& acc,
                                      unsigned long long a,
                                      unsigned long long b) {
    asm("fma.rn.f32x2 %0, %1, %2, %0;" : "+l"(acc) : "l"(a), "l"(b));
}
__device__ __forceinline__ float fold2(unsigned long long v) {
    float lo, hi;
    asm("mov.b64 {%0, %1}, %2;" : "=f"(lo), "=f"(hi) : "l"(v));
    return lo + hi;
}

// ---- mbarrier + bulk-copy helpers ----
__device__ __forceinline__ uint32_t s2u(const void* p) {
    return (uint32_t)__cvta_generic_to_shared(p);
}
__device__ __forceinline__ void mbar_init(uint32_t a, uint32_t cnt) {
    asm volatile("mbarrier.init.shared.b64 [%0], %1;" :: "r"(a), "r"(cnt) : "memory");
}
__device__ __forceinline__ void mbar_expect(uint32_t a, uint32_t bytes) {
    asm volatile("mbarrier.arrive.expect_tx.shared.b64 _, [%0], %1;"
                 :: "r"(a), "r"(bytes) : "memory");
}
__device__ __forceinline__ void bulk_g2s(uint32_t dst, const void* src,
                                         uint32_t bytes, uint32_t mbar) {
    asm volatile("cp.async.bulk.shared::cta.global.mbarrier::complete_tx::bytes "
                 "[%0], [%1], %2, [%3];"
                 :: "r"(dst), "l"(src), "r"(bytes), "r"(mbar) : "memory");
}
__device__ __forceinline__ void mbar_wait(uint32_t a, uint32_t parity) {
    asm volatile(
        "{\n\t"
        ".reg .pred P1;\n\t"
        "WAIT_LOOP_%=:\n\t"
        "mbarrier.try_wait.parity.acquire.cta.shared::cta.b64 P1, [%0], %1, 0x989680;\n\t"
        "@P1 bra.uni WAIT_DONE_%=;\n\t"
        "bra.uni WAIT_LOOP_%=;\n\t"
        "WAIT_DONE_%=:\n\t"
        "}"
        :: "r"(a), "r"(parity) : "memory");
}

// ---- software grid barrier (single-wave grid; replay-safe) ----
__device__ __forceinline__ void gridbar(unsigned* cnt) {
    __syncthreads();
    if (threadIdx.x == 0) {
        __threadfence();
        atomicAdd(cnt, 1u);
        while (*(volatile unsigned*)cnt < NBLK) { }
        __threadfence();
    }
    __syncthreads();
}

__global__ void __launch_bounds__(NTHR, 1)
fused_kernel(const float* __restrict__ x, const float* __restrict__ W,
             const float* __restrict__ bias, const float* __restrict__ gamma,
             const float* __restrict__ beta, float* __restrict__ out) {
    extern __shared__ __align__(16) float dynsm[];
    __shared__ __align__(8) unsigned long long mbar[2];
    __shared__ float ys[40 * 16];
    __shared__ float sred[STEPN][16];
    __shared__ float sd[STEPN];
    __shared__ float s_r[8];
    __shared__ float s_tot;

    const int tid = threadIdx.x;
    const int bid = blockIdx.x;
    const int rh  = bid >> 6;
    const int r0  = rh * 40;
    const int ct  = bid & 63;
    const int c0  = ct * 16;

    if (tid == 0) {
        mbar_init(s2u(&mbar[0]), 1);
        mbar_init(s2u(&mbar[1]), 1);
    }

    // ---- phase 0: W reorg into g_Wt (swizzled rows), split across all blocks
    // block handles ct = bid&63, chunks [rh*4, rh*4+4)
    {
#pragma unroll
        for (int i = tid; i < 2048; i += NTHR) {   // 4 ch x 16 c x 32 v
            int ch = (rh << 2) + (i >> 9);
            int j = i & 511;
            int c = j >> 5, v = j & 31;
            float4 val = *(const float4*)(W + (c0 + c) * D + ch * 128 + v * 4);
            int dstw = (v * 4 + c * 8) & 127;
            *(float4*)(g_Wt + ((ct * 8 + ch) * 16 + c) * 128 + dstw) = val;
        }
    }

    // ---- phase 1: q rows (blocks 0..79), chunk-major swizzled store ----
    if (bid < BS) {
        const int n = bid;
        const int b = n % NBATCH;
        const int s = n / NBATCH;
        const int rb = b * STEPN;
        const int rot = (n & 15) << 3;

        float pd[STEPN] = {0.f, 0.f, 0.f, 0.f, 0.f};
        const float* xn = x + n * D;
        for (int j = tid; j < D; j += NTHR) {
            float v = xn[j];
#pragma unroll
            for (int t = 0; t < STEPN; t++)
                pd[t] += x[(rb + t) * D + j] * v;
        }
#pragma unroll
        for (int t = 0; t < STEPN; t++) {
            float v = pd[t];
#pragma unroll
            for (int o = 16; o > 0; o >>= 1)
                v += __shfl_down_sync(0xffffffffu, v, o);
            if ((tid & 31) == 0) sred[t][tid >> 5] = v;
        }
        __syncthreads();
        if (tid < STEPN) {
            float v = 0.f;
#pragma unroll
            for (int w = 0; w < 16; w++) v += sred[tid][w];
            sd[tid] = ALPHA * v;
        }
        __syncthreads();
        for (int i = tid; i < D; i += NTHR) {
            float g = 0.f;
            for (int t = 0; t <= s; t++) {
                float xv = x[(rb + t) * D + i];
                g = g * (1.f - ALPHA * xv * xv) + xv * sd[t];
            }
            g_qt[(i >> 7) * (80 * 128) + n * 128 + (((i & 127) + rot) & 127)] = g;
        }
    }

    gridbar(&g_bar0);

    // ================= phase 2: GEMM, bulk-copy double-buffer ===============
    {
        const int w  = tid >> 5;
        const int lane = tid & 31;
        const int rg = lane >> 2;
        const int cg = lane & 3;
        const int w8 = w * 8;

        // precompute smem word offsets (stage-relative)
        int qoff[5][2], woff[4][2];
#pragma unroll
        for (int m = 0; m < 5; m++) {
            int row = rg * 5 + m;
            int rot = ((r0 + row) & 15) << 3;
#pragma unroll
            for (int qd = 0; qd < 2; qd++)
                qoff[m][qd] = row * 128 + ((w8 + qd * 4 + rot) & 127);
        }
#pragma unroll
        for (int cc = 0; cc < 4; cc++) {
            int rc = cc * 4 + cg;
#pragma unroll
            for (int qd = 0; qd < 2; qd++)
                woff[cc][qd] = QCH_FL + rc * 128 + ((w8 + qd * 4 + (rc << 3)) & 127);
        }

        unsigned long long acc[5][4];
#pragma unroll
        for (int m = 0; m < 5; m++)
#pragma unroll
            for (int c = 0; c < 4; c++) acc[m][c] = 0ull;

        auto issue = [&](int ch, int buf) {
            uint32_t mb = s2u(&mbar[buf]);
            uint32_t dq = s2u(dynsm + buf * STG_FL);
            uint32_t dw = s2u(dynsm + buf * STG_FL + QCH_FL);
            mbar_expect(mb, CHUNK_BYTES);
            bulk_g2s(dq, g_qt + ch * (80 * 128) + r0 * 128, QCH_FL * 4, mb);
            bulk_g2s(dw, g_Wt + (ct * 8 + ch) * (16 * 128), WCH_FL * 4, mb);
        };

        if (tid == 0) { issue(0, 0); issue(1, 1); }

        unsigned ph0 = 0, ph1 = 0;
        for (int ch = 0; ch < 8; ch++) {
            const int buf = ch & 1;
            if (buf == 0) { mbar_wait(s2u(&mbar[0]), ph0); ph0 ^= 1; }
            else          { mbar_wait(s2u(&mbar[1]), ph1); ph1 ^= 1; }

            const float* bb = dynsm + buf * STG_FL;
#pragma unroll
            for (int qd = 0; qd < 2; qd++) {
                ulonglong2 qv[5];
#pragma unroll
                for (int m = 0; m < 5; m++)
                    qv[m] = *(const ulonglong2*)(bb + qoff[m][qd]);
#pragma unroll
                for (int cc = 0; cc < 4; cc++) {
                    ulonglong2 wv = *(const ulonglong2*)(bb + woff[cc][qd]);
#pragma unroll
                    for (int m = 0; m < 5; m++) {
                        ffma2(acc[m][cc], qv[m].x, wv.x);
                        ffma2(acc[m][cc], qv[m].y, wv.y);
                    }
                }
            }
            __syncthreads();   // all lanes done with this buffer
            if (ch + 2 < 8 && tid == 0) issue(ch + 2, buf);
        }

        // stage folded partials (aliases stage buffers, dead now)
        float* stg = dynsm;
        {
            float* dst = stg + w * 640 + lane * 20;
#pragma unroll
            for (int m = 0; m < 5; m++)
#pragma unroll
                for (int cc = 0; cc < 4; cc++)
                    dst[m * 4 + cc] = fold2(acc[m][cc]);
        }
        __syncthreads();

        // 16-way reduce + bias; write y
        for (int idx = tid; idx < 640; idx += NTHR) {
            const int row = idx >> 4, col = idx & 15;
            const int rg2 = row / 5, m = row - rg2 * 5;
            const int cg2 = col & 3, cc = col >> 2;
            const int off = (rg2 * 4 + cg2) * 20 + m * 4 + cc;
            float s = 0.f;
#pragma unroll
            for (int ww = 0; ww < 16; ww++)
                s += stg[ww * 640 + off];
            const float yv = s + bias[c0 + col];
            g_y[(r0 + row) * D + c0 + col] = yv;
            ys[row * 16 + col] = yv;
        }
        __syncthreads();

        // per-column partial stats over this block's 40 rows
        if (tid < 16) {
            float su = 0.f, sq = 0.f;
#pragma unroll
            for (int r = 0; r < 40; r++) {
                float v = ys[r * 16 + tid];
                su += v;
                sq += v * v;
            }
            g_csum[rh][c0 + tid] = su;
            g_csq[rh][c0 + tid]  = sq;
        }
    }

    gridbar(&g_bar1);

    // ================= phase 3: BN + relu + row L2-normalize =================
    {
        const bool act = (bid < BS) && (tid < 256);
        float z[4];
        float ss = 0.f;
        int k0 = tid * 4;
        if (act) {
            const int n = bid;
            float4 y4  = *(const float4*)(g_y + n * D + k0);
            float4 s04 = *(const float4*)(&g_csum[0][k0]);
            float4 s14 = *(const float4*)(&g_csum[1][k0]);
            float4 q04 = *(const float4*)(&g_csq[0][k0]);
            float4 q14 = *(const float4*)(&g_csq[1][k0]);
            float4 ga4 = *(const float4*)(gamma + k0);
            float4 be4 = *(const float4*)(beta + k0);

            const float inv = 1.f / (float)BS;
            float mu, var, rstd;
            mu = (s04.x + s14.x) * inv; var = (q04.x + q14.x) * inv - mu * mu;
            rstd = rsqrtf(var + 1e-5f);
            z[0] = fmaxf((y4.x - mu) * rstd * ga4.x + be4.x, 0.f);
            mu = (s04.y + s14.y) * inv; var = (q04.y + q14.y) * inv - mu * mu;
            rstd = rsqrtf(var + 1e-5f);
            z[1] = fmaxf((y4.y - mu) * rstd * ga4.y + be4.y, 0.f);
            mu = (s04.z + s14.z) * inv; var = (q04.z + q14.z) * inv - mu * mu;
            rstd = rsqrtf(var + 1e-5f);
            z[2] = fmaxf((y4.z - mu) * rstd * ga4.z + be4.z, 0.f);
            mu = (s04.w + s14.w) * inv; var = (q04.w + q14.w) * inv - mu * mu;
            rstd = rsqrtf(var + 1e-5f);
            z[3] = fmaxf((y4.w - mu) * rstd * ga4.w + be4.w, 0.f);

            ss = z[0] * z[0] + z[1] * z[1] + z[2] * z[2] + z[3] * z[3];
#pragma unroll
            for (int o = 16; o > 0; o >>= 1)
                ss += __shfl_down_sync(0xffffffffu, ss, o);
            if ((tid & 31) == 0) s_r[tid >> 5] = ss;
        }
        __syncthreads();
        if (act && tid == 0) {
            float t = 0.f;
#pragma unroll
            for (int w = 0; w < 8; w++) t += s_r[w];
            s_tot = 1.f / fmaxf(sqrtf(t), 1e-12f);
        }
        __syncthreads();
        if (act) {
            float sc = s_tot;
            float4 o4 = make_float4(z[0] * sc, z[1] * sc, z[2] * sc, z[3] * sc);
            *(float4*)(out + bid * D + k0) = o4;
        }
    }

    // ---- depart + replay-safe reset of barrier state ----
    if (threadIdx.x == 0) {
        __threadfence();
        unsigned old = atomicAdd(&g_depart, 1u);
        if (old == NBLK - 1) {
            g_bar0 = 0;
            g_bar1 = 0;
            __threadfence();
            g_depart = 0;
            __threadfence();
        }
    }
}

extern "C" void kernel_launch(void* const* d_in, const int* in_sizes, int n_in,
                              void* d_out, int out_size) {
    (void)in_sizes; (void)n_in; (void)out_size;
    const float* x     = (const float*)d_in[0];
    const float* W     = (const float*)d_in[1];
    const float* bias  = (const float*)d_in[2];
    const float* gamma = (const float*)d_in[3];
    const float* beta  = (const float*)d_in[4];
    float* out = (float*)d_out;

    static int configured = 0;
    if (!configured) {
        cudaFuncSetAttribute(fused_kernel,
                             cudaFuncAttributeMaxDynamicSharedMemorySize,
                             DYN_FL * (int)sizeof(float));
        configured = 1;
    }
    fused_kernel<<<NBLK, NTHR, DYN_FL * sizeof(float)>>>(x, W, bias, gamma, beta, out);
}